// round 5
// baseline (speedup 1.0000x reference)
#include <cuda_runtime.h>
#include <cuda_bf16.h>
#include <stdint.h>
#include <math.h>

// ---------------------------------------------------------------------------
// Shapes (fixed)
#define TOK   4096
#define DIN   4096
#define DOUT  4096
#define ELEMS ((size_t)DOUT * (size_t)DIN)

#define FAST_DECAY 0.95f
#define FAST_LR    0.05f
#define SLOW_DECAY 0.99f
#define SLOW_LR    0.01f
#define HOMEO_TARGET 5.0

// CTA tile 128x128x32(bf16), 8 warps (4m x 2n), warp tile 32x64, 3-stage cp.async
#define BK      32
#define NCHUNK  (4096 / BK)          // 128
#define NSTAGE  3
#define DYN_SMEM 122880              // max stage layout: 3 * 4 * 128 * 80

// ---------------------------------------------------------------------------
// Scratch
__device__ __nv_bfloat16 g_whi[ELEMS], g_wlo[ELEMS];     // w_eff split, K-major
__device__ __nv_bfloat16 g_xhi[ELEMS], g_xlo[ELEMS];     // X split [TOK, DIN]
__device__ __nv_bfloat16 g_yrhi[ELEMS], g_yrlo[ELEMS];   // relu(Y) split [TOK, DOUT]
__device__ double g_partials[1024];
__device__ float  g_factor;

// ---------------------------------------------------------------------------
__device__ __forceinline__ uint32_t smem_u32(const void* p) {
    uint32_t a;
    asm("{ .reg .u64 t; cvta.to.shared.u64 t, %1; cvt.u32.u64 %0, t; }" : "=r"(a) : "l"(p));
    return a;
}
__device__ __forceinline__ void mma_bf16(float* c, const uint32_t* a, const uint32_t* b) {
    asm volatile(
        "mma.sync.aligned.m16n8k16.row.col.f32.bf16.bf16.f32 "
        "{%0,%1,%2,%3}, {%4,%5,%6,%7}, {%8,%9}, {%0,%1,%2,%3};"
        : "+f"(c[0]), "+f"(c[1]), "+f"(c[2]), "+f"(c[3])
        : "r"(a[0]), "r"(a[1]), "r"(a[2]), "r"(a[3]), "r"(b[0]), "r"(b[1]));
}
#define LDSM4(R, A) \
    asm volatile("ldmatrix.sync.aligned.m8n8.x4.shared.b16 {%0,%1,%2,%3}, [%4];" \
        : "=r"((R)[0]), "=r"((R)[1]), "=r"((R)[2]), "=r"((R)[3]) : "r"(A))
#define LDSM4T(R, A) \
    asm volatile("ldmatrix.sync.aligned.m8n8.x4.trans.shared.b16 {%0,%1,%2,%3}, [%4];" \
        : "=r"((R)[0]), "=r"((R)[1]), "=r"((R)[2]), "=r"((R)[3]) : "r"(A))
#define CP_ASYNC16(dst, src) \
    asm volatile("cp.async.cg.shared.global [%0], [%1], 16;" :: "r"(dst), "l"(src))
#define CP_COMMIT() asm volatile("cp.async.commit_group;" ::: "memory")
#define CP_WAIT(n)  asm volatile("cp.async.wait_group %0;" :: "n"(n) : "memory")

// ---------------------------------------------------------------------------
// Kernel: per-row bitnet quantize + combine traces; split to bf16 hi/lo
__global__ __launch_bounds__(256) void k_quant_split(
    const float* __restrict__ w, const float* __restrict__ fast, const float* __restrict__ slow,
    __nv_bfloat16* __restrict__ whi, __nv_bfloat16* __restrict__ wlo)
{
    const int row = blockIdx.x;
    const size_t base = (size_t)row * DIN;
    const int tid = threadIdx.x;

    float s = 0.f;
    for (int i = tid; i < DIN; i += 256) s += fabsf(w[base + i]);
    __shared__ float red[256];
    red[tid] = s;
    __syncthreads();
    #pragma unroll
    for (int off = 128; off > 0; off >>= 1) {
        if (tid < off) red[tid] += red[tid + off];
        __syncthreads();
    }
    float scale = fmaxf(red[0] * (1.0f / (float)DIN), 1e-5f);
    const float inv_scale = 1.0f / scale;

    for (int i = tid; i < DIN; i += 256) {
        const size_t idx = base + i;
        float q = rintf(w[idx] * inv_scale);
        q = fminf(fmaxf(q, -1.0f), 1.0f);
        float v = q * scale + 0.1f * fast[idx] + 0.05f * slow[idx];
        __nv_bfloat16 h = __float2bfloat16_rn(v);
        whi[idx] = h;
        wlo[idx] = __float2bfloat16_rn(v - __bfloat162float(h));
    }
}

// ---------------------------------------------------------------------------
// Kernel: elementwise split fp32 -> bf16 hi/lo
__global__ __launch_bounds__(256) void k_split(
    const float* __restrict__ in, __nv_bfloat16* __restrict__ hi, __nv_bfloat16* __restrict__ lo)
{
    const size_t i = ((size_t)blockIdx.x * 256 + threadIdx.x) * 4;
    float4 v = *(const float4*)(in + i);
    union { __nv_bfloat16 b[4]; uint64_t u; } H, L;
    float f[4] = {v.x, v.y, v.z, v.w};
    #pragma unroll
    for (int j = 0; j < 4; j++) {
        __nv_bfloat16 h = __float2bfloat16_rn(f[j]);
        H.b[j] = h;
        L.b[j] = __float2bfloat16_rn(f[j] - __bfloat162float(h));
    }
    *(uint64_t*)(hi + i) = H.u;
    *(uint64_t*)(lo + i) = L.u;
}

// ---------------------------------------------------------------------------
// bf16x3 GEMM via mma.sync + ldmatrix + 3-stage cp.async pipeline.
// MODE 0 (NT): D[m][n] = sum_k A[am+m][k]*B[bn+n][k]; epilogue writes y + relu split.
// MODE 1 (TT): D[m][n] = sum_k A[k][am+m]*B[k][bn+n]; epilogue EMA + sumsq partials.
// ---------------------------------------------------------------------------
template<int MODE>
__global__ __launch_bounds__(256) void k_gemm_mma(
    const __nv_bfloat16* __restrict__ Ahi, const __nv_bfloat16* __restrict__ Alo,
    const __nv_bfloat16* __restrict__ Bhi, const __nv_bfloat16* __restrict__ Blo,
    const float* __restrict__ fast, float* __restrict__ out,
    __nv_bfloat16* __restrict__ ohi, __nv_bfloat16* __restrict__ olo)
{
    constexpr bool TRANS = (MODE == 1);
    constexpr int PITCH = TRANS ? 68 : 20;           // u32 per smem row
    constexpr int ROWS  = TRANS ? 32 : 128;
    constexpr int TILEU = ROWS * PITCH;
    constexpr int STAGEU = 4 * TILEU;
    // gmem element stride between consecutive k-chunks
    constexpr size_t CH_STRIDE = TRANS ? ((size_t)BK * 4096) : (size_t)BK;

    extern __shared__ uint32_t smem[];
    __shared__ double dred[256];

    const int tid  = threadIdx.x;
    const int lane = tid & 31;
    const int wid  = tid >> 5;
    const int g    = lane >> 2;
    const int tig  = lane & 3;

    // supertile swizzle: 4 groups x (32 m-tiles x 8 n-tiles)
    const int bid   = blockIdx.x;
    const int group = bid >> 8;
    const int rem   = bid & 255;
    const int am  = (rem >> 3) * 128;
    const int bn  = (group * 8 + (rem & 7)) * 128;

    const int wm = (wid & 3) * 32;
    const int wn = (wid >> 2) * 64;

    const __nv_bfloat16* const srcs[4] = {Ahi, Alo, Bhi, Blo};
    const int cbase[4] = {am, am, bn, bn};

    const uint32_t sm0 = smem_u32(smem);

    // ---- per-thread loader bases (8 transfers/stage: 4 ops x 2) ----
    const __nv_bfloat16* src0[8];
    uint32_t dst_off[8];   // byte offset within a stage
    #pragma unroll
    for (int op = 0; op < 4; op++)
        #pragma unroll
        for (int j = 0; j < 2; j++) {
            const int i = tid + j * 256;
            const int row = TRANS ? (i >> 4) : (i >> 2);
            const int q   = TRANS ? (i & 15) : (i & 3);
            if (!TRANS)
                src0[op * 2 + j] = srcs[op] + (size_t)(cbase[op] + row) * 4096 + q * 8;
            else
                src0[op * 2 + j] = srcs[op] + (size_t)row * 4096 + cbase[op] + q * 8;
            dst_off[op * 2 + j] = (uint32_t)((op * TILEU + row * PITCH + q * 4) * 4);
        }

    // per-lane ldmatrix base offsets (bytes within a tile)
    uint32_t a_base, b_base;
    if (!TRANS) {
        const int ld_row = ((lane >> 3) & 1) * 8 + (lane & 7);
        const int ld_kb  = (lane >> 4) * 16;
        a_base = (uint32_t)((wm + ld_row) * 80 + ld_kb);
        b_base = (uint32_t)((wn + ld_row) * 80 + ld_kb);
    } else {
        const int ld_kr = (lane >> 4) * 8 + (lane & 7);
        const int ld_cb = ((lane >> 3) & 1) * 16;
        a_base = (uint32_t)(ld_kr * 272 + wm * 2 + ld_cb);
        b_base = (uint32_t)(ld_kr * 272 + wn * 2 + ld_cb);
    }

    float acc[2][8][4];
    #pragma unroll
    for (int mt = 0; mt < 2; mt++)
        #pragma unroll
        for (int nt = 0; nt < 8; nt++)
            #pragma unroll
            for (int r = 0; r < 4; r++) acc[mt][nt][r] = 0.f;

    // ---- issue helper (macro to keep addresses simple) ----
    #define ISSUE_STAGE(stage, chunk) do {                                          \
        const uint32_t sdst = sm0 + (uint32_t)(stage) * (STAGEU * 4);               \
        const size_t soff = (size_t)(chunk) * CH_STRIDE;                            \
        _Pragma("unroll")                                                           \
        for (int t = 0; t < 8; t++)                                                 \
            CP_ASYNC16(sdst + dst_off[t], src0[t] + soff);                          \
        CP_COMMIT();                                                                \
    } while (0)

    // prologue: stages 0,1 <- chunks 0,1
    ISSUE_STAGE(0, 0);
    ISSUE_STAGE(1, 1);

    int stage_c = 0;        // stage holding chunk c
    for (int c = 0; c < NCHUNK; c++) {
        if (c + 2 < NCHUNK) { CP_WAIT(1); } else { CP_WAIT(0); }
        __syncthreads();

        // issue chunk c+2 into the stage freed by chunk c-1
        if (c + 2 < NCHUNK) {
            const int stage_n = (stage_c + 2 >= NSTAGE) ? (stage_c + 2 - NSTAGE) : (stage_c + 2);
            ISSUE_STAGE(stage_n, c + 2);
        }

        // compute from stage_c
        const uint32_t stg = sm0 + (uint32_t)stage_c * (STAGEU * 4);
        #pragma unroll
        for (int ks = 0; ks < 2; ks++) {
            uint32_t a[2][2][4];
            #pragma unroll
            for (int mt = 0; mt < 2; mt++)
                #pragma unroll
                for (int t = 0; t < 2; t++) {
                    uint32_t addr;
                    if (!TRANS) addr = stg + t * (TILEU * 4) + a_base + mt * 1280 + ks * 32;
                    else        addr = stg + t * (TILEU * 4) + a_base + mt * 32 + ks * 4352;
                    if (!TRANS) { LDSM4(a[mt][t], addr); } else { LDSM4T(a[mt][t], addr); }
                }
            #pragma unroll
            for (int p = 0; p < 4; p++) {
                uint32_t bh[4], bl[4];
                if (!TRANS) {
                    LDSM4(bh, stg + 2 * (TILEU * 4) + b_base + p * 1280 + ks * 32);
                    LDSM4(bl, stg + 3 * (TILEU * 4) + b_base + p * 1280 + ks * 32);
                } else {
                    LDSM4T(bh, stg + 2 * (TILEU * 4) + b_base + p * 32 + ks * 4352);
                    LDSM4T(bl, stg + 3 * (TILEU * 4) + b_base + p * 32 + ks * 4352);
                }
                uint32_t bh0[2] = {bh[0], bh[2]}, bh1[2] = {bh[1], bh[3]};
                uint32_t bl0[2] = {bl[0], bl[2]}, bl1[2] = {bl[1], bl[3]};
                // term-major ordering: same-acc MMAs are 4 apart (deeper tensor ILP)
                mma_bf16(acc[0][2*p],   a[0][0], bh0);
                mma_bf16(acc[0][2*p+1], a[0][0], bh1);
                mma_bf16(acc[1][2*p],   a[1][0], bh0);
                mma_bf16(acc[1][2*p+1], a[1][0], bh1);
                mma_bf16(acc[0][2*p],   a[0][0], bl0);
                mma_bf16(acc[0][2*p+1], a[0][0], bl1);
                mma_bf16(acc[1][2*p],   a[1][0], bl0);
                mma_bf16(acc[1][2*p+1], a[1][0], bl1);
                mma_bf16(acc[0][2*p],   a[0][1], bh0);
                mma_bf16(acc[0][2*p+1], a[0][1], bh1);
                mma_bf16(acc[1][2*p],   a[1][1], bh0);
                mma_bf16(acc[1][2*p+1], a[1][1], bh1);
            }
        }
        stage_c = (stage_c + 1 >= NSTAGE) ? 0 : (stage_c + 1);
    }
    #undef ISSUE_STAGE

    // ---- epilogue ----
    double ss = 0.0;
    const float inv_tok = 1.0f / (float)TOK;
    #pragma unroll
    for (int mt = 0; mt < 2; mt++) {
        const int r0 = am + wm + mt * 16 + g;
        #pragma unroll
        for (int nt = 0; nt < 8; nt++) {
            const int col = bn + wn + nt * 8 + tig * 2;
            #pragma unroll
            for (int half = 0; half < 2; half++) {
                const int r = r0 + half * 8;
                const float d0 = acc[mt][nt][half * 2 + 0];
                const float d1 = acc[mt][nt][half * 2 + 1];
                const size_t o = (size_t)r * 4096 + col;
                if (MODE == 0) {
                    *(float2*)(out + o) = make_float2(d0, d1);
                    const float r0f = fmaxf(d0, 0.f), r1f = fmaxf(d1, 0.f);
                    union { __nv_bfloat16 b[2]; uint32_t u; } H, L;
                    H.b[0] = __float2bfloat16_rn(r0f);
                    H.b[1] = __float2bfloat16_rn(r1f);
                    L.b[0] = __float2bfloat16_rn(r0f - __bfloat162float(H.b[0]));
                    L.b[1] = __float2bfloat16_rn(r1f - __bfloat162float(H.b[1]));
                    *(uint32_t*)(ohi + o) = H.u;
                    *(uint32_t*)(olo + o) = L.u;
                } else {
                    const float2 fa = *(const float2*)(fast + o);
                    float2 v;
                    v.x = FAST_DECAY * fa.x + FAST_LR * (d0 * inv_tok);
                    v.y = FAST_DECAY * fa.y + FAST_LR * (d1 * inv_tok);
                    *(float2*)(out + o) = v;
                    ss += (double)v.x * v.x + (double)v.y * v.y;
                }
            }
        }
    }
    if (MODE == 1) {
        dred[tid] = ss;
        __syncthreads();
        #pragma unroll
        for (int off = 128; off > 0; off >>= 1) {
            if (tid < off) dred[tid] += dred[tid + off];
            __syncthreads();
        }
        if (tid == 0) g_partials[blockIdx.x] = dred[0];
    }
}

// ---------------------------------------------------------------------------
__global__ void k_norm_factor()
{
    __shared__ double red[256];
    const int tid = threadIdx.x;
    double s = 0.0;
    for (int i = tid; i < 1024; i += 256) s += g_partials[i];
    red[tid] = s;
    __syncthreads();
    #pragma unroll
    for (int off = 128; off > 0; off >>= 1) {
        if (tid < off) red[tid] += red[tid + off];
        __syncthreads();
    }
    if (tid == 0) {
        const double norm = sqrt(red[0]);
        g_factor = (norm > HOMEO_TARGET) ? (float)(HOMEO_TARGET / (norm + 1e-6)) : 1.0f;
    }
}

__global__ __launch_bounds__(256) void k_finalize(
    const float* __restrict__ slow, float* __restrict__ fout, float* __restrict__ sout)
{
    const float fac = g_factor;
    const size_t i = (size_t)blockIdx.x * blockDim.x + threadIdx.x;
    float4 f = ((const float4*)fout)[i];
    f.x *= fac; f.y *= fac; f.z *= fac; f.w *= fac;
    ((float4*)fout)[i] = f;
    const float4 sl = ((const float4*)slow)[i];
    float4 so;
    so.x = SLOW_DECAY * sl.x + SLOW_LR * f.x;
    so.y = SLOW_DECAY * sl.y + SLOW_LR * f.y;
    so.z = SLOW_DECAY * sl.z + SLOW_LR * f.z;
    so.w = SLOW_DECAY * sl.w + SLOW_LR * f.w;
    ((float4*)sout)[i] = so;
}

// ---------------------------------------------------------------------------
extern "C" void kernel_launch(void* const* d_in, const int* in_sizes, int n_in,
                              void* d_out, int out_size)
{
    const float* x    = (const float*)d_in[0];
    const float* w    = (const float*)d_in[1];
    const float* fast = (const float*)d_in[2];
    const float* slow = (const float*)d_in[3];

    float* out   = (float*)d_out;
    float* y_out = out;
    float* f_out = out + (size_t)TOK * DOUT;
    float* s_out = f_out + ELEMS;

    __nv_bfloat16 *whi, *wlo, *xhi, *xlo, *yrhi, *yrlo;
    cudaGetSymbolAddress((void**)&whi,  g_whi);
    cudaGetSymbolAddress((void**)&wlo,  g_wlo);
    cudaGetSymbolAddress((void**)&xhi,  g_xhi);
    cudaGetSymbolAddress((void**)&xlo,  g_xlo);
    cudaGetSymbolAddress((void**)&yrhi, g_yrhi);
    cudaGetSymbolAddress((void**)&yrlo, g_yrlo);

    cudaFuncSetAttribute(k_gemm_mma<0>, cudaFuncAttributeMaxDynamicSharedMemorySize, DYN_SMEM);
    cudaFuncSetAttribute(k_gemm_mma<1>, cudaFuncAttributeMaxDynamicSharedMemorySize, DYN_SMEM);

    // 1) w_eff = quantize(w) + 0.1*fast + 0.05*slow -> bf16 hi/lo
    k_quant_split<<<DOUT, 256>>>(w, fast, slow, whi, wlo);
    // 2) X -> bf16 hi/lo (used by BOTH GEMMs)
    k_split<<<(unsigned)(ELEMS / 4 / 256), 256>>>(x, xhi, xlo);
    // 3) Y = X @ w_eff^T; epilogue emits relu(Y) bf16 hi/lo
    k_gemm_mma<0><<<1024, 256, DYN_SMEM>>>(xhi, xlo, whi, wlo, nullptr, y_out, yrhi, yrlo);
    // 4) new_fast (unscaled) = 0.95*fast + 0.05*(reluY^T @ X)/TOK, + partials
    k_gemm_mma<1><<<1024, 256, DYN_SMEM>>>(yrhi, yrlo, xhi, xlo, fast, f_out, nullptr, nullptr);
    // 5) norm -> factor
    k_norm_factor<<<1, 256>>>();
    // 6) scale fast, compute slow
    k_finalize<<<(unsigned)(ELEMS / 4 / 256), 256>>>(slow, f_out, s_out);
}

// round 6
// speedup vs baseline: 1.1526x; 1.1526x over previous
#include <cuda_runtime.h>
#include <cuda_bf16.h>
#include <stdint.h>
#include <math.h>

// ---------------------------------------------------------------------------
// Shapes (fixed)
#define TOK   4096
#define DIN   4096
#define DOUT  4096
#define ELEMS ((size_t)DOUT * (size_t)DIN)

#define FAST_DECAY 0.95f
#define FAST_LR    0.05f
#define SLOW_DECAY 0.99f
#define SLOW_LR    0.01f
#define HOMEO_TARGET 5.0

// CTA tile 128x128x32(bf16), 8 warps (4m x 2n), warp tile 32x64, 2-stage cp.async
// 2 stages x 4 tiles x 128 x 80B = 81920 B -> 2 CTAs/SM (occupancy!)
#define BK      32
#define NCHUNK  (4096 / BK)          // 128
#define NSTAGE  2
#define DYN_SMEM 81920

// ---------------------------------------------------------------------------
// Scratch
__device__ __nv_bfloat16 g_whi[ELEMS], g_wlo[ELEMS];     // w_eff split, K-major
__device__ __nv_bfloat16 g_xhi[ELEMS], g_xlo[ELEMS];     // X split [TOK, DIN]
__device__ __nv_bfloat16 g_yrhi[ELEMS], g_yrlo[ELEMS];   // relu(Y) split [TOK, DOUT]
__device__ double g_partials[1024];
__device__ float  g_factor;

// ---------------------------------------------------------------------------
__device__ __forceinline__ uint32_t smem_u32(const void* p) {
    uint32_t a;
    asm("{ .reg .u64 t; cvta.to.shared.u64 t, %1; cvt.u32.u64 %0, t; }" : "=r"(a) : "l"(p));
    return a;
}
__device__ __forceinline__ void mma_bf16(float* c, const uint32_t* a, const uint32_t* b) {
    asm volatile(
        "mma.sync.aligned.m16n8k16.row.col.f32.bf16.bf16.f32 "
        "{%0,%1,%2,%3}, {%4,%5,%6,%7}, {%8,%9}, {%0,%1,%2,%3};"
        : "+f"(c[0]), "+f"(c[1]), "+f"(c[2]), "+f"(c[3])
        : "r"(a[0]), "r"(a[1]), "r"(a[2]), "r"(a[3]), "r"(b[0]), "r"(b[1]));
}
#define LDSM4(R, A) \
    asm volatile("ldmatrix.sync.aligned.m8n8.x4.shared.b16 {%0,%1,%2,%3}, [%4];" \
        : "=r"((R)[0]), "=r"((R)[1]), "=r"((R)[2]), "=r"((R)[3]) : "r"(A))
#define LDSM4T(R, A) \
    asm volatile("ldmatrix.sync.aligned.m8n8.x4.trans.shared.b16 {%0,%1,%2,%3}, [%4];" \
        : "=r"((R)[0]), "=r"((R)[1]), "=r"((R)[2]), "=r"((R)[3]) : "r"(A))
#define CP_ASYNC16(dst, src) \
    asm volatile("cp.async.cg.shared.global [%0], [%1], 16;" :: "r"(dst), "l"(src))
#define CP_COMMIT() asm volatile("cp.async.commit_group;" ::: "memory")
#define CP_WAIT(n)  asm volatile("cp.async.wait_group %0;" :: "n"(n) : "memory")

// ---------------------------------------------------------------------------
// Kernel: per-row bitnet quantize + combine traces; split to bf16 hi/lo
__global__ __launch_bounds__(256) void k_quant_split(
    const float* __restrict__ w, const float* __restrict__ fast, const float* __restrict__ slow,
    __nv_bfloat16* __restrict__ whi, __nv_bfloat16* __restrict__ wlo)
{
    const int row = blockIdx.x;
    const size_t base = (size_t)row * DIN;
    const int tid = threadIdx.x;

    float s = 0.f;
    for (int i = tid; i < DIN; i += 256) s += fabsf(w[base + i]);
    __shared__ float red[256];
    red[tid] = s;
    __syncthreads();
    #pragma unroll
    for (int off = 128; off > 0; off >>= 1) {
        if (tid < off) red[tid] += red[tid + off];
        __syncthreads();
    }
    float scale = fmaxf(red[0] * (1.0f / (float)DIN), 1e-5f);
    const float inv_scale = 1.0f / scale;

    for (int i = tid; i < DIN; i += 256) {
        const size_t idx = base + i;
        float q = rintf(w[idx] * inv_scale);
        q = fminf(fmaxf(q, -1.0f), 1.0f);
        float v = q * scale + 0.1f * fast[idx] + 0.05f * slow[idx];
        __nv_bfloat16 h = __float2bfloat16_rn(v);
        whi[idx] = h;
        wlo[idx] = __float2bfloat16_rn(v - __bfloat162float(h));
    }
}

// ---------------------------------------------------------------------------
// Kernel: elementwise split fp32 -> bf16 hi/lo
__global__ __launch_bounds__(256) void k_split(
    const float* __restrict__ in, __nv_bfloat16* __restrict__ hi, __nv_bfloat16* __restrict__ lo)
{
    const size_t i = ((size_t)blockIdx.x * 256 + threadIdx.x) * 4;
    float4 v = *(const float4*)(in + i);
    union { __nv_bfloat16 b[4]; uint64_t u; } H, L;
    float f[4] = {v.x, v.y, v.z, v.w};
    #pragma unroll
    for (int j = 0; j < 4; j++) {
        __nv_bfloat16 h = __float2bfloat16_rn(f[j]);
        H.b[j] = h;
        L.b[j] = __float2bfloat16_rn(f[j] - __bfloat162float(h));
    }
    *(uint64_t*)(hi + i) = H.u;
    *(uint64_t*)(lo + i) = L.u;
}

// ---------------------------------------------------------------------------
// bf16x3 GEMM via mma.sync + ldmatrix + 2-stage cp.async, 2 CTAs/SM.
// MODE 0 (NT): D[m][n] = sum_k A[am+m][k]*B[bn+n][k]; epilogue writes y + relu split.
// MODE 1 (TT): D[m][n] = sum_k A[k][am+m]*B[k][bn+n]; epilogue EMA + sumsq partials.
// ---------------------------------------------------------------------------
template<int MODE>
__global__ __launch_bounds__(256, 2) void k_gemm_mma(
    const __nv_bfloat16* __restrict__ Ahi, const __nv_bfloat16* __restrict__ Alo,
    const __nv_bfloat16* __restrict__ Bhi, const __nv_bfloat16* __restrict__ Blo,
    const float* __restrict__ fast, float* __restrict__ out,
    __nv_bfloat16* __restrict__ ohi, __nv_bfloat16* __restrict__ olo)
{
    constexpr bool TRANS = (MODE == 1);
    constexpr int PITCH = TRANS ? 68 : 20;           // u32 per smem row
    constexpr int ROWS  = TRANS ? 32 : 128;
    constexpr int TILEU = ROWS * PITCH;
    constexpr int STAGEU = 4 * TILEU;
    constexpr size_t CH_STRIDE = TRANS ? ((size_t)BK * 4096) : (size_t)BK;

    extern __shared__ uint32_t smem[];
    __shared__ double dred[256];

    const int tid  = threadIdx.x;
    const int lane = tid & 31;
    const int wid  = tid >> 5;
    const int g    = lane >> 2;
    const int tig  = lane & 3;

    // supertile swizzle: 4 groups x (32 m-tiles x 8 n-tiles)
    const int bid   = blockIdx.x;
    const int group = bid >> 8;
    const int rem   = bid & 255;
    const int am  = (rem >> 3) * 128;
    const int bn  = (group * 8 + (rem & 7)) * 128;

    const int wm = (wid & 3) * 32;
    const int wn = (wid >> 2) * 64;

    const __nv_bfloat16* const srcs[4] = {Ahi, Alo, Bhi, Blo};
    const int cbase[4] = {am, am, bn, bn};

    const uint32_t sm0 = smem_u32(smem);

    // ---- per-thread loader bases (8 transfers/stage: 4 ops x 2) ----
    const __nv_bfloat16* src0[8];
    uint32_t dst_off[8];   // byte offset within a stage
    #pragma unroll
    for (int op = 0; op < 4; op++)
        #pragma unroll
        for (int j = 0; j < 2; j++) {
            const int i = tid + j * 256;
            const int row = TRANS ? (i >> 4) : (i >> 2);
            const int q   = TRANS ? (i & 15) : (i & 3);
            if (!TRANS)
                src0[op * 2 + j] = srcs[op] + (size_t)(cbase[op] + row) * 4096 + q * 8;
            else
                src0[op * 2 + j] = srcs[op] + (size_t)row * 4096 + cbase[op] + q * 8;
            dst_off[op * 2 + j] = (uint32_t)((op * TILEU + row * PITCH + q * 4) * 4);
        }

    // per-lane ldmatrix base offsets (bytes within a tile)
    uint32_t a_base, b_base;
    if (!TRANS) {
        const int ld_row = ((lane >> 3) & 1) * 8 + (lane & 7);
        const int ld_kb  = (lane >> 4) * 16;
        a_base = (uint32_t)((wm + ld_row) * 80 + ld_kb);
        b_base = (uint32_t)((wn + ld_row) * 80 + ld_kb);
    } else {
        const int ld_kr = (lane >> 4) * 8 + (lane & 7);
        const int ld_cb = ((lane >> 3) & 1) * 16;
        a_base = (uint32_t)(ld_kr * 272 + wm * 2 + ld_cb);
        b_base = (uint32_t)(ld_kr * 272 + wn * 2 + ld_cb);
    }

    float acc[2][8][4];
    #pragma unroll
    for (int mt = 0; mt < 2; mt++)
        #pragma unroll
        for (int nt = 0; nt < 8; nt++)
            #pragma unroll
            for (int r = 0; r < 4; r++) acc[mt][nt][r] = 0.f;

    #define ISSUE_STAGE(stage, chunk) do {                                          \
        const uint32_t sdst = sm0 + (uint32_t)(stage) * (STAGEU * 4);               \
        const size_t soff = (size_t)(chunk) * CH_STRIDE;                            \
        _Pragma("unroll")                                                           \
        for (int t = 0; t < 8; t++)                                                 \
            CP_ASYNC16(sdst + dst_off[t], src0[t] + soff);                          \
        CP_COMMIT();                                                                \
    } while (0)

    // prologue: stages 0,1 <- chunks 0,1
    ISSUE_STAGE(0, 0);
    ISSUE_STAGE(1, 1);

    for (int c = 0; c < NCHUNK; c++) {
        const int stage_c = c & 1;
        // chunk c complete (allow chunk c+1 to remain in flight)
        if (c + 1 < NCHUNK) { CP_WAIT(1); } else { CP_WAIT(0); }
        __syncthreads();

        // compute from stage_c
        const uint32_t stg = sm0 + (uint32_t)stage_c * (STAGEU * 4);
        #pragma unroll
        for (int ks = 0; ks < 2; ks++) {
            uint32_t a[2][2][4];
            #pragma unroll
            for (int mt = 0; mt < 2; mt++)
                #pragma unroll
                for (int t = 0; t < 2; t++) {
                    uint32_t addr;
                    if (!TRANS) addr = stg + t * (TILEU * 4) + a_base + mt * 1280 + ks * 32;
                    else        addr = stg + t * (TILEU * 4) + a_base + mt * 32 + ks * 4352;
                    if (!TRANS) { LDSM4(a[mt][t], addr); } else { LDSM4T(a[mt][t], addr); }
                }
            #pragma unroll
            for (int p = 0; p < 4; p++) {
                uint32_t bh[4], bl[4];
                if (!TRANS) {
                    LDSM4(bh, stg + 2 * (TILEU * 4) + b_base + p * 1280 + ks * 32);
                    LDSM4(bl, stg + 3 * (TILEU * 4) + b_base + p * 1280 + ks * 32);
                } else {
                    LDSM4T(bh, stg + 2 * (TILEU * 4) + b_base + p * 32 + ks * 4352);
                    LDSM4T(bl, stg + 3 * (TILEU * 4) + b_base + p * 32 + ks * 4352);
                }
                uint32_t bh0[2] = {bh[0], bh[2]}, bh1[2] = {bh[1], bh[3]};
                uint32_t bl0[2] = {bl[0], bl[2]}, bl1[2] = {bl[1], bl[3]};
                // term-major ordering: same-acc MMAs are 4 apart (tensor ILP)
                mma_bf16(acc[0][2*p],   a[0][0], bh0);
                mma_bf16(acc[0][2*p+1], a[0][0], bh1);
                mma_bf16(acc[1][2*p],   a[1][0], bh0);
                mma_bf16(acc[1][2*p+1], a[1][0], bh1);
                mma_bf16(acc[0][2*p],   a[0][0], bl0);
                mma_bf16(acc[0][2*p+1], a[0][0], bl1);
                mma_bf16(acc[1][2*p],   a[1][0], bl0);
                mma_bf16(acc[1][2*p+1], a[1][0], bl1);
                mma_bf16(acc[0][2*p],   a[0][1], bh0);
                mma_bf16(acc[0][2*p+1], a[0][1], bh1);
                mma_bf16(acc[1][2*p],   a[1][1], bh0);
                mma_bf16(acc[1][2*p+1], a[1][1], bh1);
            }
        }

        // all warps done reading stage_c -> refill it with chunk c+2
        __syncthreads();
        if (c + 2 < NCHUNK) ISSUE_STAGE(stage_c, c + 2);
    }
    #undef ISSUE_STAGE

    // ---- epilogue ----
    double ss = 0.0;
    const float inv_tok = 1.0f / (float)TOK;
    #pragma unroll
    for (int mt = 0; mt < 2; mt++) {
        const int r0 = am + wm + mt * 16 + g;
        #pragma unroll
        for (int nt = 0; nt < 8; nt++) {
            const int col = bn + wn + nt * 8 + tig * 2;
            #pragma unroll
            for (int half = 0; half < 2; half++) {
                const int r = r0 + half * 8;
                const float d0 = acc[mt][nt][half * 2 + 0];
                const float d1 = acc[mt][nt][half * 2 + 1];
                const size_t o = (size_t)r * 4096 + col;
                if (MODE == 0) {
                    *(float2*)(out + o) = make_float2(d0, d1);
                    const float r0f = fmaxf(d0, 0.f), r1f = fmaxf(d1, 0.f);
                    union { __nv_bfloat16 b[2]; uint32_t u; } H, L;
                    H.b[0] = __float2bfloat16_rn(r0f);
                    H.b[1] = __float2bfloat16_rn(r1f);
                    L.b[0] = __float2bfloat16_rn(r0f - __bfloat162float(H.b[0]));
                    L.b[1] = __float2bfloat16_rn(r1f - __bfloat162float(H.b[1]));
                    *(uint32_t*)(ohi + o) = H.u;
                    *(uint32_t*)(olo + o) = L.u;
                } else {
                    const float2 fa = *(const float2*)(fast + o);
                    float2 v;
                    v.x = FAST_DECAY * fa.x + FAST_LR * (d0 * inv_tok);
                    v.y = FAST_DECAY * fa.y + FAST_LR * (d1 * inv_tok);
                    *(float2*)(out + o) = v;
                    ss += (double)v.x * v.x + (double)v.y * v.y;
                }
            }
        }
    }
    if (MODE == 1) {
        dred[tid] = ss;
        __syncthreads();
        #pragma unroll
        for (int off = 128; off > 0; off >>= 1) {
            if (tid < off) dred[tid] += dred[tid + off];
            __syncthreads();
        }
        if (tid == 0) g_partials[blockIdx.x] = dred[0];
    }
}

// ---------------------------------------------------------------------------
__global__ void k_norm_factor()
{
    __shared__ double red[256];
    const int tid = threadIdx.x;
    double s = 0.0;
    for (int i = tid; i < 1024; i += 256) s += g_partials[i];
    red[tid] = s;
    __syncthreads();
    #pragma unroll
    for (int off = 128; off > 0; off >>= 1) {
        if (tid < off) red[tid] += red[tid + off];
        __syncthreads();
    }
    if (tid == 0) {
        const double norm = sqrt(red[0]);
        g_factor = (norm > HOMEO_TARGET) ? (float)(HOMEO_TARGET / (norm + 1e-6)) : 1.0f;
    }
}

__global__ __launch_bounds__(256) void k_finalize(
    const float* __restrict__ slow, float* __restrict__ fout, float* __restrict__ sout)
{
    const float fac = g_factor;
    const size_t i = (size_t)blockIdx.x * blockDim.x + threadIdx.x;
    float4 f = ((const float4*)fout)[i];
    f.x *= fac; f.y *= fac; f.z *= fac; f.w *= fac;
    ((float4*)fout)[i] = f;
    const float4 sl = ((const float4*)slow)[i];
    float4 so;
    so.x = SLOW_DECAY * sl.x + SLOW_LR * f.x;
    so.y = SLOW_DECAY * sl.y + SLOW_LR * f.y;
    so.z = SLOW_DECAY * sl.z + SLOW_LR * f.z;
    so.w = SLOW_DECAY * sl.w + SLOW_LR * f.w;
    ((float4*)sout)[i] = so;
}

// ---------------------------------------------------------------------------
extern "C" void kernel_launch(void* const* d_in, const int* in_sizes, int n_in,
                              void* d_out, int out_size)
{
    const float* x    = (const float*)d_in[0];
    const float* w    = (const float*)d_in[1];
    const float* fast = (const float*)d_in[2];
    const float* slow = (const float*)d_in[3];

    float* out   = (float*)d_out;
    float* y_out = out;
    float* f_out = out + (size_t)TOK * DOUT;
    float* s_out = f_out + ELEMS;

    __nv_bfloat16 *whi, *wlo, *xhi, *xlo, *yrhi, *yrlo;
    cudaGetSymbolAddress((void**)&whi,  g_whi);
    cudaGetSymbolAddress((void**)&wlo,  g_wlo);
    cudaGetSymbolAddress((void**)&xhi,  g_xhi);
    cudaGetSymbolAddress((void**)&xlo,  g_xlo);
    cudaGetSymbolAddress((void**)&yrhi, g_yrhi);
    cudaGetSymbolAddress((void**)&yrlo, g_yrlo);

    cudaFuncSetAttribute(k_gemm_mma<0>, cudaFuncAttributeMaxDynamicSharedMemorySize, DYN_SMEM);
    cudaFuncSetAttribute(k_gemm_mma<1>, cudaFuncAttributeMaxDynamicSharedMemorySize, DYN_SMEM);

    // 1) w_eff = quantize(w) + 0.1*fast + 0.05*slow -> bf16 hi/lo
    k_quant_split<<<DOUT, 256>>>(w, fast, slow, whi, wlo);
    // 2) X -> bf16 hi/lo (used by BOTH GEMMs)
    k_split<<<(unsigned)(ELEMS / 4 / 256), 256>>>(x, xhi, xlo);
    // 3) Y = X @ w_eff^T; epilogue emits relu(Y) bf16 hi/lo
    k_gemm_mma<0><<<1024, 256, DYN_SMEM>>>(xhi, xlo, whi, wlo, nullptr, y_out, yrhi, yrlo);
    // 4) new_fast (unscaled) = 0.95*fast + 0.05*(reluY^T @ X)/TOK, + partials
    k_gemm_mma<1><<<1024, 256, DYN_SMEM>>>(yrhi, yrlo, xhi, xlo, fast, f_out, nullptr, nullptr);
    // 5) norm -> factor
    k_norm_factor<<<1, 256>>>();
    // 6) scale fast, compute slow
    k_finalize<<<(unsigned)(ELEMS / 4 / 256), 256>>>(slow, f_out, s_out);
}

// round 7
// speedup vs baseline: 1.1596x; 1.0061x over previous
#include <cuda_runtime.h>
#include <cuda_bf16.h>
#include <stdint.h>
#include <math.h>

// ---------------------------------------------------------------------------
// Shapes (fixed)
#define TOK   4096
#define DIN   4096
#define DOUT  4096
#define ELEMS ((size_t)DOUT * (size_t)DIN)

#define FAST_DECAY 0.95f
#define FAST_LR    0.05f
#define SLOW_DECAY 0.99f
#define SLOW_LR    0.01f
#define HOMEO_TARGET 5.0

// CTA tile 128x128x32(bf16), 8 warps (4m x 2n), warp tile 32x64, 2-stage cp.async
#define BK      32
#define NCHUNK  (4096 / BK)          // 128
#define DYN_SMEM 81920               // 2 stages x 4 tiles x 128 x 80B -> 2 CTAs/SM

// ---------------------------------------------------------------------------
// Scratch
__device__ __nv_bfloat16 g_whi[ELEMS], g_wlo[ELEMS];     // w_eff split, K-major
__device__ __nv_bfloat16 g_xhi[ELEMS], g_xlo[ELEMS];     // X split [TOK, DIN]
__device__ __nv_bfloat16 g_yrhi[ELEMS], g_yrlo[ELEMS];   // relu(Y) split [TOK, DOUT]
__device__ double g_partials[1024];
__device__ float  g_factor;

// ---------------------------------------------------------------------------
__device__ __forceinline__ uint32_t smem_u32(const void* p) {
    uint32_t a;
    asm("{ .reg .u64 t; cvta.to.shared.u64 t, %1; cvt.u32.u64 %0, t; }" : "=r"(a) : "l"(p));
    return a;
}
__device__ __forceinline__ void mma_bf16(float* c, const uint32_t* a, const uint32_t* b) {
    asm volatile(
        "mma.sync.aligned.m16n8k16.row.col.f32.bf16.bf16.f32 "
        "{%0,%1,%2,%3}, {%4,%5,%6,%7}, {%8,%9}, {%0,%1,%2,%3};"
        : "+f"(c[0]), "+f"(c[1]), "+f"(c[2]), "+f"(c[3])
        : "r"(a[0]), "r"(a[1]), "r"(a[2]), "r"(a[3]), "r"(b[0]), "r"(b[1]));
}
#define LDSM4(R, A) \
    asm volatile("ldmatrix.sync.aligned.m8n8.x4.shared.b16 {%0,%1,%2,%3}, [%4];" \
        : "=r"((R)[0]), "=r"((R)[1]), "=r"((R)[2]), "=r"((R)[3]) : "r"(A))
#define LDSM4T(R, A) \
    asm volatile("ldmatrix.sync.aligned.m8n8.x4.trans.shared.b16 {%0,%1,%2,%3}, [%4];" \
        : "=r"((R)[0]), "=r"((R)[1]), "=r"((R)[2]), "=r"((R)[3]) : "r"(A))
#define CP_ASYNC16(dst, src) \
    asm volatile("cp.async.cg.shared.global [%0], [%1], 16;" :: "r"(dst), "l"(src))
#define CP_COMMIT() asm volatile("cp.async.commit_group;" ::: "memory")
#define CP_WAIT(n)  asm volatile("cp.async.wait_group %0;" :: "n"(n) : "memory")

// ---------------------------------------------------------------------------
// Fused prep: blocks [0,4096): per-row quantize+combine w_eff -> whi/wlo
//             blocks [4096,20480): elementwise split X -> xhi/xlo
__global__ __launch_bounds__(256) void k_prep(
    const float* __restrict__ w, const float* __restrict__ fast, const float* __restrict__ slow,
    const float* __restrict__ x,
    __nv_bfloat16* __restrict__ whi, __nv_bfloat16* __restrict__ wlo,
    __nv_bfloat16* __restrict__ xhi, __nv_bfloat16* __restrict__ xlo)
{
    const int tid = threadIdx.x;
    if (blockIdx.x >= 4096) {
        const size_t i = ((size_t)(blockIdx.x - 4096) * 256 + tid) * 4;
        float4 v = *(const float4*)(x + i);
        union { __nv_bfloat16 b[4]; uint64_t u; } H, L;
        float f[4] = {v.x, v.y, v.z, v.w};
        #pragma unroll
        for (int j = 0; j < 4; j++) {
            __nv_bfloat16 h = __float2bfloat16_rn(f[j]);
            H.b[j] = h;
            L.b[j] = __float2bfloat16_rn(f[j] - __bfloat162float(h));
        }
        *(uint64_t*)(xhi + i) = H.u;
        *(uint64_t*)(xlo + i) = L.u;
        return;
    }
    const int row = blockIdx.x;
    const size_t base = (size_t)row * DIN;

    float s = 0.f;
    for (int i = tid; i < DIN; i += 256) s += fabsf(w[base + i]);
    __shared__ float red[256];
    red[tid] = s;
    __syncthreads();
    #pragma unroll
    for (int off = 128; off > 0; off >>= 1) {
        if (tid < off) red[tid] += red[tid + off];
        __syncthreads();
    }
    float scale = fmaxf(red[0] * (1.0f / (float)DIN), 1e-5f);
    const float inv_scale = 1.0f / scale;

    for (int i = tid; i < DIN; i += 256) {
        const size_t idx = base + i;
        float q = rintf(w[idx] * inv_scale);
        q = fminf(fmaxf(q, -1.0f), 1.0f);
        float v = q * scale + 0.1f * fast[idx] + 0.05f * slow[idx];
        __nv_bfloat16 h = __float2bfloat16_rn(v);
        whi[idx] = h;
        wlo[idx] = __float2bfloat16_rn(v - __bfloat162float(h));
    }
}

// ---------------------------------------------------------------------------
// bf16x3 GEMM via mma.sync + ldmatrix + 2-stage cp.async, 2 CTAs/SM.
// MODE 0 (NT): D[m][n] = sum_k A[am+m][k]*B[bn+n][k]; epilogue writes y + relu split.
// MODE 1 (TT): D[m][n] = sum_k A[k][am+m]*B[k][bn+n]; epilogue EMA + sumsq partials.
// ---------------------------------------------------------------------------
template<int MODE>
__global__ __launch_bounds__(256, 2) void k_gemm_mma(
    const __nv_bfloat16* __restrict__ Ahi, const __nv_bfloat16* __restrict__ Alo,
    const __nv_bfloat16* __restrict__ Bhi, const __nv_bfloat16* __restrict__ Blo,
    const float* __restrict__ fast, float* __restrict__ out,
    __nv_bfloat16* __restrict__ ohi, __nv_bfloat16* __restrict__ olo)
{
    constexpr bool TRANS = (MODE == 1);
    constexpr int PITCH = TRANS ? 68 : 20;           // u32 per smem row
    constexpr int ROWS  = TRANS ? 32 : 128;
    constexpr int TILEU = ROWS * PITCH;
    constexpr int STAGEU = 4 * TILEU;
    constexpr size_t CH_STRIDE = TRANS ? ((size_t)BK * 4096) : (size_t)BK;

    extern __shared__ uint32_t smem[];
    __shared__ double dred[256];

    const int tid  = threadIdx.x;
    const int lane = tid & 31;
    const int wid  = tid >> 5;
    const int g    = lane >> 2;
    const int tig  = lane & 3;

    // supertile swizzle: 4 groups x (32 m-tiles x 8 n-tiles)
    const int bid   = blockIdx.x;
    const int group = bid >> 8;
    const int rem   = bid & 255;
    const int am  = (rem >> 3) * 128;
    const int bn  = (group * 8 + (rem & 7)) * 128;

    const int wm = (wid & 3) * 32;
    const int wn = (wid >> 2) * 64;

    const __nv_bfloat16* const srcs[4] = {Ahi, Alo, Bhi, Blo};
    const int cbase[4] = {am, am, bn, bn};

    const uint32_t sm0 = smem_u32(smem);

    // ---- per-thread loader bases (8 transfers/stage: 4 ops x 2) ----
    const __nv_bfloat16* src0[8];
    uint32_t dst_off[8];
    #pragma unroll
    for (int op = 0; op < 4; op++)
        #pragma unroll
        for (int j = 0; j < 2; j++) {
            const int i = tid + j * 256;
            const int row = TRANS ? (i >> 4) : (i >> 2);
            const int q   = TRANS ? (i & 15) : (i & 3);
            if (!TRANS)
                src0[op * 2 + j] = srcs[op] + (size_t)(cbase[op] + row) * 4096 + q * 8;
            else
                src0[op * 2 + j] = srcs[op] + (size_t)row * 4096 + cbase[op] + q * 8;
            dst_off[op * 2 + j] = (uint32_t)((op * TILEU + row * PITCH + q * 4) * 4);
        }

    // per-lane ldmatrix base offsets (bytes within a tile)
    uint32_t a_base, b_base;
    if (!TRANS) {
        const int ld_row = ((lane >> 3) & 1) * 8 + (lane & 7);
        const int ld_kb  = (lane >> 4) * 16;
        a_base = (uint32_t)((wm + ld_row) * 80 + ld_kb);
        b_base = (uint32_t)((wn + ld_row) * 80 + ld_kb);
    } else {
        const int ld_kr = (lane >> 4) * 8 + (lane & 7);
        const int ld_cb = ((lane >> 3) & 1) * 16;
        a_base = (uint32_t)(ld_kr * 272 + wm * 2 + ld_cb);
        b_base = (uint32_t)(ld_kr * 272 + wn * 2 + ld_cb);
    }

    float acc[2][8][4];
    #pragma unroll
    for (int mt = 0; mt < 2; mt++)
        #pragma unroll
        for (int nt = 0; nt < 8; nt++)
            #pragma unroll
            for (int r = 0; r < 4; r++) acc[mt][nt][r] = 0.f;

    #define ISSUE_STAGE(stage, chunk) do {                                          \
        const uint32_t sdst = sm0 + (uint32_t)(stage) * (STAGEU * 4);               \
        const size_t soff = (size_t)(chunk) * CH_STRIDE;                            \
        _Pragma("unroll")                                                           \
        for (int t = 0; t < 8; t++)                                                 \
            CP_ASYNC16(sdst + dst_off[t], src0[t] + soff);                          \
        CP_COMMIT();                                                                \
    } while (0)

    ISSUE_STAGE(0, 0);
    ISSUE_STAGE(1, 1);

    for (int c = 0; c < NCHUNK; c++) {
        const int stage_c = c & 1;
        if (c + 1 < NCHUNK) { CP_WAIT(1); } else { CP_WAIT(0); }
        __syncthreads();

        const uint32_t stg = sm0 + (uint32_t)stage_c * (STAGEU * 4);
        #pragma unroll
        for (int ks = 0; ks < 2; ks++) {
            // A fragments for this ks (hi and lo terms)
            uint32_t a[2][2][4];
            #pragma unroll
            for (int mt = 0; mt < 2; mt++)
                #pragma unroll
                for (int t = 0; t < 2; t++) {
                    uint32_t addr;
                    if (!TRANS) addr = stg + t * (TILEU * 4) + a_base + mt * 1280 + ks * 32;
                    else        addr = stg + t * (TILEU * 4) + a_base + mt * 32 + ks * 4352;
                    if (!TRANS) { LDSM4(a[mt][t], addr); } else { LDSM4T(a[mt][t], addr); }
                }
            // B in pairs of p: 8 LDSM then 24 MMAs (acc reuse distance 8)
            #pragma unroll
            for (int pp = 0; pp < 2; pp++) {
                uint32_t bh[2][4], bl[2][4];
                #pragma unroll
                for (int q = 0; q < 2; q++) {
                    const int p = pp * 2 + q;
                    if (!TRANS) {
                        LDSM4(bh[q], stg + 2 * (TILEU * 4) + b_base + p * 1280 + ks * 32);
                        LDSM4(bl[q], stg + 3 * (TILEU * 4) + b_base + p * 1280 + ks * 32);
                    } else {
                        LDSM4T(bh[q], stg + 2 * (TILEU * 4) + b_base + p * 32 + ks * 4352);
                        LDSM4T(bl[q], stg + 3 * (TILEU * 4) + b_base + p * 32 + ks * 4352);
                    }
                }
                // term hi*hi
                #pragma unroll
                for (int q = 0; q < 2; q++) {
                    const int p = pp * 2 + q;
                    uint32_t b0[2] = {bh[q][0], bh[q][2]}, b1[2] = {bh[q][1], bh[q][3]};
                    mma_bf16(acc[0][2*p],   a[0][0], b0);
                    mma_bf16(acc[0][2*p+1], a[0][0], b1);
                    mma_bf16(acc[1][2*p],   a[1][0], b0);
                    mma_bf16(acc[1][2*p+1], a[1][0], b1);
                }
                // term hi*lo
                #pragma unroll
                for (int q = 0; q < 2; q++) {
                    const int p = pp * 2 + q;
                    uint32_t b0[2] = {bl[q][0], bl[q][2]}, b1[2] = {bl[q][1], bl[q][3]};
                    mma_bf16(acc[0][2*p],   a[0][0], b0);
                    mma_bf16(acc[0][2*p+1], a[0][0], b1);
                    mma_bf16(acc[1][2*p],   a[1][0], b0);
                    mma_bf16(acc[1][2*p+1], a[1][0], b1);
                }
                // term lo*hi
                #pragma unroll
                for (int q = 0; q < 2; q++) {
                    const int p = pp * 2 + q;
                    uint32_t b0[2] = {bh[q][0], bh[q][2]}, b1[2] = {bh[q][1], bh[q][3]};
                    mma_bf16(acc[0][2*p],   a[0][1], b0);
                    mma_bf16(acc[0][2*p+1], a[0][1], b1);
                    mma_bf16(acc[1][2*p],   a[1][1], b0);
                    mma_bf16(acc[1][2*p+1], a[1][1], b1);
                }
            }
        }

        __syncthreads();
        if (c + 2 < NCHUNK) ISSUE_STAGE(stage_c, c + 2);
    }
    #undef ISSUE_STAGE

    // ---- epilogue ----
    double ss = 0.0;
    const float inv_tok = 1.0f / (float)TOK;
    #pragma unroll
    for (int mt = 0; mt < 2; mt++) {
        const int r0 = am + wm + mt * 16 + g;
        #pragma unroll
        for (int nt = 0; nt < 8; nt++) {
            const int col = bn + wn + nt * 8 + tig * 2;
            #pragma unroll
            for (int half = 0; half < 2; half++) {
                const int r = r0 + half * 8;
                const float d0 = acc[mt][nt][half * 2 + 0];
                const float d1 = acc[mt][nt][half * 2 + 1];
                const size_t o = (size_t)r * 4096 + col;
                if (MODE == 0) {
                    *(float2*)(out + o) = make_float2(d0, d1);
                    const float r0f = fmaxf(d0, 0.f), r1f = fmaxf(d1, 0.f);
                    union { __nv_bfloat16 b[2]; uint32_t u; } H, L;
                    H.b[0] = __float2bfloat16_rn(r0f);
                    H.b[1] = __float2bfloat16_rn(r1f);
                    L.b[0] = __float2bfloat16_rn(r0f - __bfloat162float(H.b[0]));
                    L.b[1] = __float2bfloat16_rn(r1f - __bfloat162float(H.b[1]));
                    *(uint32_t*)(ohi + o) = H.u;
                    *(uint32_t*)(olo + o) = L.u;
                } else {
                    const float2 fa = *(const float2*)(fast + o);
                    float2 v;
                    v.x = FAST_DECAY * fa.x + FAST_LR * (d0 * inv_tok);
                    v.y = FAST_DECAY * fa.y + FAST_LR * (d1 * inv_tok);
                    *(float2*)(out + o) = v;
                    ss += (double)v.x * v.x + (double)v.y * v.y;
                }
            }
        }
    }
    if (MODE == 1) {
        dred[tid] = ss;
        __syncthreads();
        #pragma unroll
        for (int off = 128; off > 0; off >>= 1) {
            if (tid < off) dred[tid] += dred[tid + off];
            __syncthreads();
        }
        if (tid == 0) g_partials[blockIdx.x] = dred[0];
    }
}

// ---------------------------------------------------------------------------
__global__ void k_norm_factor()
{
    __shared__ double red[256];
    const int tid = threadIdx.x;
    double s = 0.0;
    for (int i = tid; i < 1024; i += 256) s += g_partials[i];
    red[tid] = s;
    __syncthreads();
    #pragma unroll
    for (int off = 128; off > 0; off >>= 1) {
        if (tid < off) red[tid] += red[tid + off];
        __syncthreads();
    }
    if (tid == 0) {
        const double norm = sqrt(red[0]);
        g_factor = (norm > HOMEO_TARGET) ? (float)(HOMEO_TARGET / (norm + 1e-6)) : 1.0f;
    }
}

__global__ __launch_bounds__(256) void k_finalize(
    const float* __restrict__ slow, float* __restrict__ fout, float* __restrict__ sout)
{
    const float fac = g_factor;
    const size_t i = (size_t)blockIdx.x * blockDim.x + threadIdx.x;
    float4 f = ((const float4*)fout)[i];
    f.x *= fac; f.y *= fac; f.z *= fac; f.w *= fac;
    ((float4*)fout)[i] = f;
    const float4 sl = ((const float4*)slow)[i];
    float4 so;
    so.x = SLOW_DECAY * sl.x + SLOW_LR * f.x;
    so.y = SLOW_DECAY * sl.y + SLOW_LR * f.y;
    so.z = SLOW_DECAY * sl.z + SLOW_LR * f.z;
    so.w = SLOW_DECAY * sl.w + SLOW_LR * f.w;
    ((float4*)sout)[i] = so;
}

// ---------------------------------------------------------------------------
extern "C" void kernel_launch(void* const* d_in, const int* in_sizes, int n_in,
                              void* d_out, int out_size)
{
    const float* x    = (const float*)d_in[0];
    const float* w    = (const float*)d_in[1];
    const float* fast = (const float*)d_in[2];
    const float* slow = (const float*)d_in[3];

    float* out   = (float*)d_out;
    float* y_out = out;
    float* f_out = out + (size_t)TOK * DOUT;
    float* s_out = f_out + ELEMS;

    __nv_bfloat16 *whi, *wlo, *xhi, *xlo, *yrhi, *yrlo;
    cudaGetSymbolAddress((void**)&whi,  g_whi);
    cudaGetSymbolAddress((void**)&wlo,  g_wlo);
    cudaGetSymbolAddress((void**)&xhi,  g_xhi);
    cudaGetSymbolAddress((void**)&xlo,  g_xlo);
    cudaGetSymbolAddress((void**)&yrhi, g_yrhi);
    cudaGetSymbolAddress((void**)&yrlo, g_yrlo);

    cudaFuncSetAttribute(k_gemm_mma<0>, cudaFuncAttributeMaxDynamicSharedMemorySize, DYN_SMEM);
    cudaFuncSetAttribute(k_gemm_mma<1>, cudaFuncAttributeMaxDynamicSharedMemorySize, DYN_SMEM);

    // 1) fused prep: w_eff quantize+split AND X split
    k_prep<<<4096 + 16384, 256>>>(w, fast, slow, x, whi, wlo, xhi, xlo);
    // 2) Y = X @ w_eff^T; epilogue emits relu(Y) bf16 hi/lo
    k_gemm_mma<0><<<1024, 256, DYN_SMEM>>>(xhi, xlo, whi, wlo, nullptr, y_out, yrhi, yrlo);
    // 3) new_fast (unscaled) = 0.95*fast + 0.05*(reluY^T @ X)/TOK, + partials
    k_gemm_mma<1><<<1024, 256, DYN_SMEM>>>(yrhi, yrlo, xhi, xlo, fast, f_out, nullptr, nullptr);
    // 4) norm -> factor
    k_norm_factor<<<1, 256>>>();
    // 5) scale fast, compute slow
    k_finalize<<<(unsigned)(ELEMS / 4 / 256), 256>>>(slow, f_out, s_out);
}

// round 8
// speedup vs baseline: 1.1706x; 1.0095x over previous
#include <cuda_runtime.h>
#include <cuda_bf16.h>
#include <stdint.h>
#include <math.h>

// ---------------------------------------------------------------------------
// Shapes (fixed)
#define TOK   4096
#define DIN   4096
#define DOUT  4096
#define ELEMS ((size_t)DOUT * (size_t)DIN)

#define FAST_DECAY 0.95f
#define FAST_LR    0.05f
#define SLOW_DECAY 0.99f
#define SLOW_LR    0.01f
#define HOMEO_TARGET 5.0

// CTA tile 128x128x32(bf16), 8 warps (4m x 2n), warp tile 32x64, 2-stage cp.async
#define BK      32
#define NCHUNK  (4096 / BK)          // 128
#define DYN_SMEM 81920               // 2 stages x 4 tiles x 128 x 80B -> 2 CTAs/SM

// ---------------------------------------------------------------------------
// Scratch
__device__ __nv_bfloat16 g_whi[ELEMS], g_wlo[ELEMS];     // w_eff split, K-major
__device__ __nv_bfloat16 g_xhi[ELEMS], g_xlo[ELEMS];     // X split [TOK, DIN]
__device__ __nv_bfloat16 g_yrhi[ELEMS], g_yrlo[ELEMS];   // relu(Y) split [TOK, DOUT]
__device__ double g_partials[1024];
__device__ float  g_factor;

// ---------------------------------------------------------------------------
__device__ __forceinline__ uint32_t smem_u32(const void* p) {
    uint32_t a;
    asm("{ .reg .u64 t; cvta.to.shared.u64 t, %1; cvt.u32.u64 %0, t; }" : "=r"(a) : "l"(p));
    return a;
}
__device__ __forceinline__ void mma_bf16(float* c, const uint32_t* a, const uint32_t* b) {
    asm volatile(
        "mma.sync.aligned.m16n8k16.row.col.f32.bf16.bf16.f32 "
        "{%0,%1,%2,%3}, {%4,%5,%6,%7}, {%8,%9}, {%0,%1,%2,%3};"
        : "+f"(c[0]), "+f"(c[1]), "+f"(c[2]), "+f"(c[3])
        : "r"(a[0]), "r"(a[1]), "r"(a[2]), "r"(a[3]), "r"(b[0]), "r"(b[1]));
}
#define LDSM4(R, A) \
    asm volatile("ldmatrix.sync.aligned.m8n8.x4.shared.b16 {%0,%1,%2,%3}, [%4];" \
        : "=r"((R)[0]), "=r"((R)[1]), "=r"((R)[2]), "=r"((R)[3]) : "r"(A))
#define LDSM4T(R, A) \
    asm volatile("ldmatrix.sync.aligned.m8n8.x4.trans.shared.b16 {%0,%1,%2,%3}, [%4];" \
        : "=r"((R)[0]), "=r"((R)[1]), "=r"((R)[2]), "=r"((R)[3]) : "r"(A))
#define CP_ASYNC16(dst, src) \
    asm volatile("cp.async.cg.shared.global [%0], [%1], 16;" :: "r"(dst), "l"(src))
#define CP_COMMIT() asm volatile("cp.async.commit_group;" ::: "memory")
#define CP_WAIT0()  asm volatile("cp.async.wait_group 0;" ::: "memory")

// ---------------------------------------------------------------------------
// Fused prep: blocks [0,4096): per-row quantize+combine w_eff -> whi/wlo
//             blocks [4096,20480): elementwise split X -> xhi/xlo
__global__ __launch_bounds__(256) void k_prep(
    const float* __restrict__ w, const float* __restrict__ fast, const float* __restrict__ slow,
    const float* __restrict__ x,
    __nv_bfloat16* __restrict__ whi, __nv_bfloat16* __restrict__ wlo,
    __nv_bfloat16* __restrict__ xhi, __nv_bfloat16* __restrict__ xlo)
{
    const int tid = threadIdx.x;
    if (blockIdx.x >= 4096) {
        const size_t i = ((size_t)(blockIdx.x - 4096) * 256 + tid) * 4;
        float4 v = *(const float4*)(x + i);
        union { __nv_bfloat16 b[4]; uint64_t u; } H, L;
        float f[4] = {v.x, v.y, v.z, v.w};
        #pragma unroll
        for (int j = 0; j < 4; j++) {
            __nv_bfloat16 h = __float2bfloat16_rn(f[j]);
            H.b[j] = h;
            L.b[j] = __float2bfloat16_rn(f[j] - __bfloat162float(h));
        }
        *(uint64_t*)(xhi + i) = H.u;
        *(uint64_t*)(xlo + i) = L.u;
        return;
    }
    const int row = blockIdx.x;
    const size_t base = (size_t)row * DIN;

    float s = 0.f;
    for (int i = tid; i < DIN; i += 256) s += fabsf(w[base + i]);
    __shared__ float red[256];
    red[tid] = s;
    __syncthreads();
    #pragma unroll
    for (int off = 128; off > 0; off >>= 1) {
        if (tid < off) red[tid] += red[tid + off];
        __syncthreads();
    }
    float scale = fmaxf(red[0] * (1.0f / (float)DIN), 1e-5f);
    const float inv_scale = 1.0f / scale;

    for (int i = tid; i < DIN; i += 256) {
        const size_t idx = base + i;
        float q = rintf(w[idx] * inv_scale);
        q = fminf(fmaxf(q, -1.0f), 1.0f);
        float v = q * scale + 0.1f * fast[idx] + 0.05f * slow[idx];
        __nv_bfloat16 h = __float2bfloat16_rn(v);
        whi[idx] = h;
        wlo[idx] = __float2bfloat16_rn(v - __bfloat162float(h));
    }
}

// ---------------------------------------------------------------------------
// bf16x3 GEMM via mma.sync + ldmatrix + 2-stage cp.async, 2 CTAs/SM,
// ONE __syncthreads per k-chunk.
// MODE 0 (NT): D[m][n] = sum_k A[am+m][k]*B[bn+n][k]; epilogue writes y + relu split.
// MODE 1 (TT): D[m][n] = sum_k A[k][am+m]*B[k][bn+n]; epilogue EMA + sumsq partials.
// ---------------------------------------------------------------------------
template<int MODE>
__global__ __launch_bounds__(256, 2) void k_gemm_mma(
    const __nv_bfloat16* __restrict__ Ahi, const __nv_bfloat16* __restrict__ Alo,
    const __nv_bfloat16* __restrict__ Bhi, const __nv_bfloat16* __restrict__ Blo,
    const float* __restrict__ fast, float* __restrict__ out,
    __nv_bfloat16* __restrict__ ohi, __nv_bfloat16* __restrict__ olo)
{
    constexpr bool TRANS = (MODE == 1);
    constexpr int PITCH = TRANS ? 68 : 20;           // u32 per smem row
    constexpr int ROWS  = TRANS ? 32 : 128;
    constexpr int TILEU = ROWS * PITCH;
    constexpr int STAGEU = 4 * TILEU;
    constexpr size_t CH_STRIDE = TRANS ? ((size_t)BK * 4096) : (size_t)BK;

    extern __shared__ uint32_t smem[];
    __shared__ double dred[256];

    const int tid  = threadIdx.x;
    const int lane = tid & 31;
    const int wid  = tid >> 5;
    const int g    = lane >> 2;
    const int tig  = lane & 3;

    // supertile swizzle: 4 groups x (32 m-tiles x 8 n-tiles)
    const int bid   = blockIdx.x;
    const int group = bid >> 8;
    const int rem   = bid & 255;
    const int am  = (rem >> 3) * 128;
    const int bn  = (group * 8 + (rem & 7)) * 128;

    const int wm = (wid & 3) * 32;
    const int wn = (wid >> 2) * 64;

    const __nv_bfloat16* const srcs[4] = {Ahi, Alo, Bhi, Blo};
    const int cbase[4] = {am, am, bn, bn};

    const uint32_t sm0 = smem_u32(smem);

    // ---- per-thread loader bases (8 transfers/stage: 4 ops x 2) ----
    const __nv_bfloat16* src0[8];
    uint32_t dst_off[8];
    #pragma unroll
    for (int op = 0; op < 4; op++)
        #pragma unroll
        for (int j = 0; j < 2; j++) {
            const int i = tid + j * 256;
            const int row = TRANS ? (i >> 4) : (i >> 2);
            const int q   = TRANS ? (i & 15) : (i & 3);
            if (!TRANS)
                src0[op * 2 + j] = srcs[op] + (size_t)(cbase[op] + row) * 4096 + q * 8;
            else
                src0[op * 2 + j] = srcs[op] + (size_t)row * 4096 + cbase[op] + q * 8;
            dst_off[op * 2 + j] = (uint32_t)((op * TILEU + row * PITCH + q * 4) * 4);
        }

    // per-lane ldmatrix base offsets (bytes within a tile)
    uint32_t a_base, b_base;
    if (!TRANS) {
        const int ld_row = ((lane >> 3) & 1) * 8 + (lane & 7);
        const int ld_kb  = (lane >> 4) * 16;
        a_base = (uint32_t)((wm + ld_row) * 80 + ld_kb);
        b_base = (uint32_t)((wn + ld_row) * 80 + ld_kb);
    } else {
        const int ld_kr = (lane >> 4) * 8 + (lane & 7);
        const int ld_cb = ((lane >> 3) & 1) * 16;
        a_base = (uint32_t)(ld_kr * 272 + wm * 2 + ld_cb);
        b_base = (uint32_t)(ld_kr * 272 + wn * 2 + ld_cb);
    }

    float acc[2][8][4];
    #pragma unroll
    for (int mt = 0; mt < 2; mt++)
        #pragma unroll
        for (int nt = 0; nt < 8; nt++)
            #pragma unroll
            for (int r = 0; r < 4; r++) acc[mt][nt][r] = 0.f;

    #define ISSUE_STAGE(stage, chunk) do {                                          \
        const uint32_t sdst = sm0 + (uint32_t)(stage) * (STAGEU * 4);               \
        const size_t soff = (size_t)(chunk) * CH_STRIDE;                            \
        _Pragma("unroll")                                                           \
        for (int t = 0; t < 8; t++)                                                 \
            CP_ASYNC16(sdst + dst_off[t], src0[t] + soff);                          \
        CP_COMMIT();                                                                \
    } while (0)

    // prologue: stage 0 <- chunk 0 (one group outstanding at any time)
    ISSUE_STAGE(0, 0);

    for (int c = 0; c < NCHUNK; c++) {
        const int stage_c = c & 1;
        // own copies of chunk c done; barrier makes ALL warps' copies visible
        // AND certifies everyone finished computing chunk c-1 (program order),
        // so the other stage is free to refill. ONE sync per chunk.
        CP_WAIT0();
        __syncthreads();
        if (c + 1 < NCHUNK) ISSUE_STAGE(stage_c ^ 1, c + 1);

        const uint32_t stg = sm0 + (uint32_t)stage_c * (STAGEU * 4);
        #pragma unroll
        for (int ks = 0; ks < 2; ks++) {
            // A fragments for this ks (hi and lo terms)
            uint32_t a[2][2][4];
            #pragma unroll
            for (int mt = 0; mt < 2; mt++)
                #pragma unroll
                for (int t = 0; t < 2; t++) {
                    uint32_t addr;
                    if (!TRANS) addr = stg + t * (TILEU * 4) + a_base + mt * 1280 + ks * 32;
                    else        addr = stg + t * (TILEU * 4) + a_base + mt * 32 + ks * 4352;
                    if (!TRANS) { LDSM4(a[mt][t], addr); } else { LDSM4T(a[mt][t], addr); }
                }
            // B in pairs of p: 8 LDSM then 24 MMAs (acc reuse distance 8)
            #pragma unroll
            for (int pp = 0; pp < 2; pp++) {
                uint32_t bh[2][4], bl[2][4];
                #pragma unroll
                for (int q = 0; q < 2; q++) {
                    const int p = pp * 2 + q;
                    if (!TRANS) {
                        LDSM4(bh[q], stg + 2 * (TILEU * 4) + b_base + p * 1280 + ks * 32);
                        LDSM4(bl[q], stg + 3 * (TILEU * 4) + b_base + p * 1280 + ks * 32);
                    } else {
                        LDSM4T(bh[q], stg + 2 * (TILEU * 4) + b_base + p * 32 + ks * 4352);
                        LDSM4T(bl[q], stg + 3 * (TILEU * 4) + b_base + p * 32 + ks * 4352);
                    }
                }
                #pragma unroll
                for (int q = 0; q < 2; q++) {
                    const int p = pp * 2 + q;
                    uint32_t b0[2] = {bh[q][0], bh[q][2]}, b1[2] = {bh[q][1], bh[q][3]};
                    mma_bf16(acc[0][2*p],   a[0][0], b0);
                    mma_bf16(acc[0][2*p+1], a[0][0], b1);
                    mma_bf16(acc[1][2*p],   a[1][0], b0);
                    mma_bf16(acc[1][2*p+1], a[1][0], b1);
                }
                #pragma unroll
                for (int q = 0; q < 2; q++) {
                    const int p = pp * 2 + q;
                    uint32_t b0[2] = {bl[q][0], bl[q][2]}, b1[2] = {bl[q][1], bl[q][3]};
                    mma_bf16(acc[0][2*p],   a[0][0], b0);
                    mma_bf16(acc[0][2*p+1], a[0][0], b1);
                    mma_bf16(acc[1][2*p],   a[1][0], b0);
                    mma_bf16(acc[1][2*p+1], a[1][0], b1);
                }
                #pragma unroll
                for (int q = 0; q < 2; q++) {
                    const int p = pp * 2 + q;
                    uint32_t b0[2] = {bh[q][0], bh[q][2]}, b1[2] = {bh[q][1], bh[q][3]};
                    mma_bf16(acc[0][2*p],   a[0][1], b0);
                    mma_bf16(acc[0][2*p+1], a[0][1], b1);
                    mma_bf16(acc[1][2*p],   a[1][1], b0);
                    mma_bf16(acc[1][2*p+1], a[1][1], b1);
                }
            }
        }
    }
    #undef ISSUE_STAGE

    // ---- epilogue ----
    double ss = 0.0;
    const float inv_tok = 1.0f / (float)TOK;
    #pragma unroll
    for (int mt = 0; mt < 2; mt++) {
        const int r0 = am + wm + mt * 16 + g;
        #pragma unroll
        for (int nt = 0; nt < 8; nt++) {
            const int col = bn + wn + nt * 8 + tig * 2;
            #pragma unroll
            for (int half = 0; half < 2; half++) {
                const int r = r0 + half * 8;
                const float d0 = acc[mt][nt][half * 2 + 0];
                const float d1 = acc[mt][nt][half * 2 + 1];
                const size_t o = (size_t)r * 4096 + col;
                if (MODE == 0) {
                    *(float2*)(out + o) = make_float2(d0, d1);
                    const float r0f = fmaxf(d0, 0.f), r1f = fmaxf(d1, 0.f);
                    union { __nv_bfloat16 b[2]; uint32_t u; } H, L;
                    H.b[0] = __float2bfloat16_rn(r0f);
                    H.b[1] = __float2bfloat16_rn(r1f);
                    L.b[0] = __float2bfloat16_rn(r0f - __bfloat162float(H.b[0]));
                    L.b[1] = __float2bfloat16_rn(r1f - __bfloat162float(H.b[1]));
                    *(uint32_t*)(ohi + o) = H.u;
                    *(uint32_t*)(olo + o) = L.u;
                } else {
                    const float2 fa = *(const float2*)(fast + o);
                    float2 v;
                    v.x = FAST_DECAY * fa.x + FAST_LR * (d0 * inv_tok);
                    v.y = FAST_DECAY * fa.y + FAST_LR * (d1 * inv_tok);
                    *(float2*)(out + o) = v;
                    ss += (double)v.x * v.x + (double)v.y * v.y;
                }
            }
        }
    }
    if (MODE == 1) {
        dred[tid] = ss;
        __syncthreads();
        #pragma unroll
        for (int off = 128; off > 0; off >>= 1) {
            if (tid < off) dred[tid] += dred[tid + off];
            __syncthreads();
        }
        if (tid == 0) g_partials[blockIdx.x] = dred[0];
    }
}

// ---------------------------------------------------------------------------
__global__ void k_norm_factor()
{
    __shared__ double red[256];
    const int tid = threadIdx.x;
    double s = 0.0;
    for (int i = tid; i < 1024; i += 256) s += g_partials[i];
    red[tid] = s;
    __syncthreads();
    #pragma unroll
    for (int off = 128; off > 0; off >>= 1) {
        if (tid < off) red[tid] += red[tid + off];
        __syncthreads();
    }
    if (tid == 0) {
        const double norm = sqrt(red[0]);
        g_factor = (norm > HOMEO_TARGET) ? (float)(HOMEO_TARGET / (norm + 1e-6)) : 1.0f;
    }
}

__global__ __launch_bounds__(256) void k_finalize(
    const float* __restrict__ slow, float* __restrict__ fout, float* __restrict__ sout)
{
    const float fac = g_factor;
    const size_t i = (size_t)blockIdx.x * blockDim.x + threadIdx.x;
    float4 f = ((const float4*)fout)[i];
    f.x *= fac; f.y *= fac; f.z *= fac; f.w *= fac;
    ((float4*)fout)[i] = f;
    const float4 sl = ((const float4*)slow)[i];
    float4 so;
    so.x = SLOW_DECAY * sl.x + SLOW_LR * f.x;
    so.y = SLOW_DECAY * sl.y + SLOW_LR * f.y;
    so.z = SLOW_DECAY * sl.z + SLOW_LR * f.z;
    so.w = SLOW_DECAY * sl.w + SLOW_LR * f.w;
    ((float4*)sout)[i] = so;
}

// ---------------------------------------------------------------------------
extern "C" void kernel_launch(void* const* d_in, const int* in_sizes, int n_in,
                              void* d_out, int out_size)
{
    const float* x    = (const float*)d_in[0];
    const float* w    = (const float*)d_in[1];
    const float* fast = (const float*)d_in[2];
    const float* slow = (const float*)d_in[3];

    float* out   = (float*)d_out;
    float* y_out = out;
    float* f_out = out + (size_t)TOK * DOUT;
    float* s_out = f_out + ELEMS;

    __nv_bfloat16 *whi, *wlo, *xhi, *xlo, *yrhi, *yrlo;
    cudaGetSymbolAddress((void**)&whi,  g_whi);
    cudaGetSymbolAddress((void**)&wlo,  g_wlo);
    cudaGetSymbolAddress((void**)&xhi,  g_xhi);
    cudaGetSymbolAddress((void**)&xlo,  g_xlo);
    cudaGetSymbolAddress((void**)&yrhi, g_yrhi);
    cudaGetSymbolAddress((void**)&yrlo, g_yrlo);

    cudaFuncSetAttribute(k_gemm_mma<0>, cudaFuncAttributeMaxDynamicSharedMemorySize, DYN_SMEM);
    cudaFuncSetAttribute(k_gemm_mma<1>, cudaFuncAttributeMaxDynamicSharedMemorySize, DYN_SMEM);

    // 1) fused prep: w_eff quantize+split AND X split
    k_prep<<<4096 + 16384, 256>>>(w, fast, slow, x, whi, wlo, xhi, xlo);
    // 2) Y = X @ w_eff^T; epilogue emits relu(Y) bf16 hi/lo
    k_gemm_mma<0><<<1024, 256, DYN_SMEM>>>(xhi, xlo, whi, wlo, nullptr, y_out, yrhi, yrlo);
    // 3) new_fast (unscaled) = 0.95*fast + 0.05*(reluY^T @ X)/TOK, + partials
    k_gemm_mma<1><<<1024, 256, DYN_SMEM>>>(yrhi, yrlo, xhi, xlo, fast, f_out, nullptr, nullptr);
    // 4) norm -> factor
    k_norm_factor<<<1, 256>>>();
    // 5) scale fast, compute slow
    k_finalize<<<(unsigned)(ELEMS / 4 / 256), 256>>>(slow, f_out, s_out);
}